// round 1
// baseline (speedup 1.0000x reference)
#include <cuda_runtime.h>
#include <math.h>

// SparseMoEGate: x[16384,4096] f32, weight[64,4096] f32
// out: [topk_idx as f32 (2T)] [topk_weight (2T)] [aux_loss (1)]

#define T_TOKENS 16384
#define C_DIM    4096
#define E_EXP    64
#define ALPHA    0.01f

#define BT     128           // tokens per block
#define BK     32            // k-chunk
#define NTH    256
#define NCHUNK (C_DIM / BK)  // 128

// smem layout (bytes)
#define XS_ROW  136                    // 32 floats + 2-float pad (17 float2)
#define XS_BUF  (BT * XS_ROW)          // 17408
#define WS_ROW  528                    // 64 float2 + pad
#define WS_BUF  (16 * WS_ROW)          // 8448
#define WS_OFF  (2 * XS_BUF)           // 34816
#define CNT_OFF (WS_OFF + 2 * WS_BUF)  // 51712
#define SMEM_BYTES (CNT_OFF + 256)     // 51968

typedef unsigned long long u64;

__device__ float g_ssum[E_EXP];
__device__ float g_cnt[E_EXP];

__device__ __forceinline__ void cp8(void* s, const void* g) {
    unsigned sa = (unsigned)__cvta_generic_to_shared(s);
    asm volatile("cp.async.ca.shared.global [%0], [%1], 8;" :: "r"(sa), "l"(g));
}
__device__ __forceinline__ void fma2(u64& d, u64 a, u64 b) {
    asm("fma.rn.f32x2 %0, %1, %2, %0;" : "+l"(d) : "l"(a), "l"(b));
}

__global__ void zero_kernel() {
    int t = threadIdx.x;
    if (t < E_EXP) { g_ssum[t] = 0.f; g_cnt[t] = 0.f; }
}

extern __shared__ char smem[];

__global__ __launch_bounds__(NTH, 2) void gate_kernel(
    const float* __restrict__ x, const float* __restrict__ w,
    float* __restrict__ out)
{
    const int tid = threadIdx.x, blk = blockIdx.x;
    const int eg = tid & 15;         // expert group (4 experts)
    const int tg = tid >> 4;         // token group (8 tokens)
    const int t0 = tg * 8;
    const float* xg = x + (size_t)blk * BT * C_DIM;

    u64 acc[8][4];
    #pragma unroll
    for (int i = 0; i < 8; i++)
        #pragma unroll
        for (int j = 0; j < 4; j++) acc[i][j] = 0ull;

    auto copy_chunk = [&](int c) {
        const int buf = c & 1, k0 = c * BK;
        char* xb = smem + buf * XS_BUF;
        #pragma unroll
        for (int it = 0; it < 8; it++) {
            int idx = tid + it * NTH;
            int row = idx >> 4, seg = idx & 15;
            cp8(xb + row * XS_ROW + seg * 8,
                xg + (size_t)row * C_DIM + k0 + seg * 2);
        }
        char* wb = smem + WS_OFF + buf * WS_BUF;
        #pragma unroll
        for (int it = 0; it < 4; it++) {
            int idx = tid + it * NTH;
            int e = idx >> 4, kp = idx & 15;
            int ep = (e & 3) * 16 + (e >> 2);   // swizzle: conflict-free LDS
            cp8(wb + kp * WS_ROW + ep * 8,
                w + (size_t)e * C_DIM + k0 + kp * 2);
        }
        asm volatile("cp.async.commit_group;");
    };

    copy_chunk(0);
    for (int c = 0; c < NCHUNK; c++) {
        if (c + 1 < NCHUNK) {
            copy_chunk(c + 1);
            asm volatile("cp.async.wait_group 1;");
        } else {
            asm volatile("cp.async.wait_group 0;");
        }
        __syncthreads();
        const char* xb = smem + (c & 1) * XS_BUF;
        const char* wb = smem + WS_OFF + (c & 1) * WS_BUF;
        #pragma unroll
        for (int kp = 0; kp < 16; kp++) {
            u64 xv[8], wv[4];
            #pragma unroll
            for (int j = 0; j < 4; j++)
                wv[j] = *(const u64*)(wb + kp * WS_ROW + (j * 16 + eg) * 8);
            #pragma unroll
            for (int i = 0; i < 8; i++)
                xv[i] = *(const u64*)(xb + (t0 + i) * XS_ROW + kp * 8);
            #pragma unroll
            for (int i = 0; i < 8; i++)
                #pragma unroll
                for (int j = 0; j < 4; j++)
                    fma2(acc[i][j], xv[i], wv[j]);
        }
        __syncthreads();
    }

    // ---- epilogue: logits -> smem [BT][65] ----
    float* lg = (float*)smem;
    const int e0 = eg * 4;
    #pragma unroll
    for (int i = 0; i < 8; i++)
        #pragma unroll
        for (int j = 0; j < 4; j++) {
            float lo, hi;
            asm("mov.b64 {%0, %1}, %2;" : "=f"(lo), "=f"(hi) : "l"(acc[i][j]));
            lg[(t0 + i) * 65 + e0 + j] = lo + hi;
        }
    int* s_cnt = (int*)(smem + CNT_OFF);
    if (tid < E_EXP) s_cnt[tid] = 0;
    __syncthreads();

    if (tid < BT) {
        float* row = lg + tid * 65;
        float v1 = -1e30f, v2 = -1e30f;
        int i1 = 0, i2 = 0;
        #pragma unroll
        for (int e = 0; e < E_EXP; e++) {
            float v = row[e];
            if (v > v1)      { v2 = v1; i2 = i1; v1 = v; i1 = e; }
            else if (v > v2) { v2 = v;  i2 = e; }
        }
        float Z = 0.f;
        #pragma unroll
        for (int e = 0; e < E_EXP; e++) {
            float ex = expf(row[e] - v1);
            row[e] = ex; Z += ex;
        }
        float rz = 1.0f / Z;
        #pragma unroll
        for (int e = 0; e < E_EXP; e++) row[e] *= rz;
        float s1 = row[i1], s2 = row[i2];
        float inv = 1.0f / (s1 + s2);
        int gt = blk * BT + tid;
        out[2 * gt]     = (float)i1;
        out[2 * gt + 1] = (float)i2;
        out[2 * T_TOKENS + 2 * gt]     = s1 * inv;
        out[2 * T_TOKENS + 2 * gt + 1] = s2 * inv;
        atomicAdd(&s_cnt[i1], 1);
        atomicAdd(&s_cnt[i2], 1);
    }
    __syncthreads();

    if (tid < E_EXP) {
        float sum = 0.f;
        for (int t = 0; t < BT; t++) sum += lg[t * 65 + tid];
        atomicAdd(&g_ssum[tid], sum);
        atomicAdd(&g_cnt[tid], (float)s_cnt[tid]);
    }
}

__global__ void finalize_kernel(float* __restrict__ out) {
    __shared__ float p[E_EXP];
    int t = threadIdx.x;
    p[t] = g_ssum[t] * g_cnt[t];
    __syncthreads();
    if (t == 0) {
        float s = 0.f;
        for (int i = 0; i < E_EXP; i++) s += p[i];
        // aux = alpha * E/(T*K*T) * sum_e cnt_e * ssum_e
        out[4 * T_TOKENS] = s * (ALPHA * (float)E_EXP /
            ((float)T_TOKENS * 2.0f * (float)T_TOKENS));
    }
}

extern "C" void kernel_launch(void* const* d_in, const int* in_sizes, int n_in,
                              void* d_out, int out_size) {
    const float* x = (const float*)d_in[0];
    const float* w = (const float*)d_in[1];
    float* out = (float*)d_out;
    cudaFuncSetAttribute(gate_kernel,
                         cudaFuncAttributeMaxDynamicSharedMemorySize, SMEM_BYTES);
    zero_kernel<<<1, 64>>>();
    gate_kernel<<<T_TOKENS / BT, NTH, SMEM_BYTES>>>(x, w, out);
    finalize_kernel<<<1, 64>>>(out);
}

// round 3
// speedup vs baseline: 1.0183x; 1.0183x over previous
#include <cuda_runtime.h>
#include <math.h>
#include <stdint.h>

// SparseMoEGate via mma.sync (HMMA) bf16x3 exact-split GEMM.
// x[16384,4096] f32, w[64,4096] f32
// out: [topk_idx as f32 (2T)] [topk_weight (2T)] [aux_loss (1)]

#define T_TOKENS 16384
#define C_DIM    4096
#define E_EXP    64
#define ALPHA    0.01f

#define BT   128              // tokens per CTA
#define NTH  256              // 8 warps
#define NKS  (C_DIM / 16)     // 256 k-steps of 16

__device__ float g_ssum[E_EXP];
__device__ float g_cnt[E_EXP];
// B fragments: [ks][nt][plane][lane*2+r] u32, 256*8*3*64 = 393216 u32 (1.5MB)
__device__ uint32_t w_frag[256 * 8 * 3 * 64];

// exact 3-way bf16 split of (even,odd) f32 pair -> packed bf16x2 (lo=even)
__device__ __forceinline__ void split3(float fe, float fo,
                                       uint32_t& h1, uint32_t& h2, uint32_t& h3) {
    asm("cvt.rn.bf16x2.f32 %0, %1, %2;" : "=r"(h1) : "f"(fo), "f"(fe));
    float ro = fo - __uint_as_float(h1 & 0xffff0000u);
    float re = fe - __uint_as_float(h1 << 16);
    asm("cvt.rn.bf16x2.f32 %0, %1, %2;" : "=r"(h2) : "f"(ro), "f"(re));
    float so = ro - __uint_as_float(h2 & 0xffff0000u);
    float se = re - __uint_as_float(h2 << 16);
    asm("cvt.rn.bf16x2.f32 %0, %1, %2;" : "=r"(h3) : "f"(so), "f"(se));
}

#define MMA(acc, A, B)                                                        \
    asm volatile(                                                             \
        "mma.sync.aligned.m16n8k16.row.col.f32.bf16.bf16.f32 "                \
        "{%0,%1,%2,%3}, {%4,%5,%6,%7}, {%8,%9}, {%0,%1,%2,%3};"               \
        : "+f"(acc[0]), "+f"(acc[1]), "+f"(acc[2]), "+f"(acc[3])              \
        : "r"(A[0]), "r"(A[1]), "r"(A[2]), "r"(A[3]), "r"(B.x), "r"(B.y))

__global__ void zero_kernel() {
    int t = threadIdx.x;
    if (t < E_EXP) { g_ssum[t] = 0.f; g_cnt[t] = 0.f; }
}

// Precompute w bf16x3 planes in mma B-fragment layout.
__global__ void prep_w(const float* __restrict__ w) {
    int i = blockIdx.x * blockDim.x + threadIdx.x;   // 131072 threads
    int r = i & 1, lane = (i >> 1) & 31, nt = (i >> 6) & 7, ks = i >> 9;
    int e = nt * 8 + (lane >> 2);
    int k = ks * 16 + r * 8 + 2 * (lane & 3);
    float fe = w[(size_t)e * C_DIM + k];
    float fo = w[(size_t)e * C_DIM + k + 1];
    uint32_t h1, h2, h3;
    split3(fe, fo, h1, h2, h3);
    int base = ((ks * 8 + nt) * 3) * 64 + lane * 2 + r;
    w_frag[base]       = h1;
    w_frag[base + 64]  = h2;
    w_frag[base + 128] = h3;
}

__global__ __launch_bounds__(NTH, 1) void gate_kernel(
    const float* __restrict__ x, float* __restrict__ out)
{
    __shared__ float lg[BT * 65];
    __shared__ int s_cnt[E_EXP];

    const int tid = threadIdx.x, blk = blockIdx.x;
    const int wid = tid >> 5, lane = tid & 31;
    const int qr = lane >> 2, qc = lane & 3;        // quad row / col
    const int trow0 = blk * BT + wid * 16 + qr;     // global token rows
    const float2* xr0 = (const float2*)(x + (size_t)trow0 * C_DIM) + qc;
    const float2* xr1 = (const float2*)(x + (size_t)(trow0 + 8) * C_DIM) + qc;
    const uint2* wf = (const uint2*)w_frag;

    if (tid < E_EXP) s_cnt[tid] = 0;

    float acc[8][4];
    #pragma unroll
    for (int nt = 0; nt < 8; nt++)
        #pragma unroll
        for (int j = 0; j < 4; j++) acc[nt][j] = 0.f;

    // A register double buffer
    float2 cur0 = xr0[0], cur1 = xr0[4], cur2 = xr1[0], cur3 = xr1[4];

    #pragma unroll 1
    for (int ks = 0; ks < NKS; ks++) {
        const int ksn = (ks + 1) & (NKS - 1);
        float2 nx0 = xr0[ksn * 8],     nx1 = xr0[ksn * 8 + 4];
        float2 nx2 = xr1[ksn * 8],     nx3 = xr1[ksn * 8 + 4];

        // split A: frag order [r0/klo, r1/klo, r0/khi, r1/khi]
        uint32_t a1[4], a2[4], a3[4];
        split3(cur0.x, cur0.y, a1[0], a2[0], a3[0]);
        split3(cur2.x, cur2.y, a1[1], a2[1], a3[1]);
        split3(cur1.x, cur1.y, a1[2], a2[2], a3[2]);
        split3(cur3.x, cur3.y, a1[3], a2[3], a3[3]);

        const int kb = ks * 768 + lane;   // ((ks*8+nt)*3+p)*32 + lane, u2 units
        uint2 b[8];

        // plane b1: pairs (a1,b1),(a2,b1),(a3,b1)
        #pragma unroll
        for (int nt = 0; nt < 8; nt++) b[nt] = wf[kb + nt * 96];
        #pragma unroll
        for (int nt = 0; nt < 8; nt++) MMA(acc[nt], a1, b[nt]);
        #pragma unroll
        for (int nt = 0; nt < 8; nt++) MMA(acc[nt], a2, b[nt]);
        #pragma unroll
        for (int nt = 0; nt < 8; nt++) MMA(acc[nt], a3, b[nt]);

        // plane b2: pairs (a1,b2),(a2,b2)
        #pragma unroll
        for (int nt = 0; nt < 8; nt++) b[nt] = wf[kb + nt * 96 + 32];
        #pragma unroll
        for (int nt = 0; nt < 8; nt++) MMA(acc[nt], a1, b[nt]);
        #pragma unroll
        for (int nt = 0; nt < 8; nt++) MMA(acc[nt], a2, b[nt]);

        // plane b3: pair (a1,b3)
        #pragma unroll
        for (int nt = 0; nt < 8; nt++) b[nt] = wf[kb + nt * 96 + 64];
        #pragma unroll
        for (int nt = 0; nt < 8; nt++) MMA(acc[nt], a1, b[nt]);

        cur0 = nx0; cur1 = nx1; cur2 = nx2; cur3 = nx3;
    }

    // scatter logits to smem: row = wid*16 + qr (+8), col = nt*8 + 2*qc (+1)
    const int lr0 = wid * 16 + qr;
    #pragma unroll
    for (int nt = 0; nt < 8; nt++) {
        const int e = nt * 8 + 2 * qc;
        lg[lr0 * 65 + e]           = acc[nt][0];
        lg[lr0 * 65 + e + 1]       = acc[nt][1];
        lg[(lr0 + 8) * 65 + e]     = acc[nt][2];
        lg[(lr0 + 8) * 65 + e + 1] = acc[nt][3];
    }
    __syncthreads();

    if (tid < BT) {
        float* row = lg + tid * 65;
        float v1 = -1e30f, v2 = -1e30f;
        int i1 = 0, i2 = 0;
        #pragma unroll
        for (int e = 0; e < E_EXP; e++) {
            float v = row[e];
            if (v > v1)      { v2 = v1; i2 = i1; v1 = v; i1 = e; }
            else if (v > v2) { v2 = v;  i2 = e; }
        }
        float Z = 0.f;
        #pragma unroll
        for (int e = 0; e < E_EXP; e++) {
            float ex = expf(row[e] - v1);
            row[e] = ex; Z += ex;
        }
        float rz = 1.0f / Z;
        #pragma unroll
        for (int e = 0; e < E_EXP; e++) row[e] *= rz;
        float s1 = row[i1], s2 = row[i2];
        float inv = 1.0f / (s1 + s2);
        int gt = blk * BT + tid;
        out[2 * gt]     = (float)i1;
        out[2 * gt + 1] = (float)i2;
        out[2 * T_TOKENS + 2 * gt]     = s1 * inv;
        out[2 * T_TOKENS + 2 * gt + 1] = s2 * inv;
        atomicAdd(&s_cnt[i1], 1);
        atomicAdd(&s_cnt[i2], 1);
    }
    __syncthreads();

    if (tid < E_EXP) {
        float sum = 0.f;
        for (int t = 0; t < BT; t++) sum += lg[t * 65 + tid];
        atomicAdd(&g_ssum[tid], sum);
        atomicAdd(&g_cnt[tid], (float)s_cnt[tid]);
    }
}

__global__ void finalize_kernel(float* __restrict__ out) {
    __shared__ float p[E_EXP];
    int t = threadIdx.x;
    p[t] = g_ssum[t] * g_cnt[t];
    __syncthreads();
    if (t == 0) {
        float s = 0.f;
        for (int i = 0; i < E_EXP; i++) s += p[i];
        out[4 * T_TOKENS] = s * (ALPHA * (float)E_EXP /
            ((float)T_TOKENS * 2.0f * (float)T_TOKENS));
    }
}

extern "C" void kernel_launch(void* const* d_in, const int* in_sizes, int n_in,
                              void* d_out, int out_size) {
    const float* x = (const float*)d_in[0];
    const float* w = (const float*)d_in[1];
    float* out = (float*)d_out;
    zero_kernel<<<1, 64>>>();
    prep_w<<<512, 256>>>(w);
    gate_kernel<<<T_TOKENS / BT, NTH>>>(x, out);
    finalize_kernel<<<1, 64>>>(out);
}

// round 4
// speedup vs baseline: 1.1910x; 1.1696x over previous
#include <cuda_runtime.h>
#include <math.h>
#include <stdint.h>

// SparseMoEGate via mma.sync (HMMA) bf16x3 exact-split GEMM.
// R4: w-fragments staged through smem (cp.async 3-stage pipeline) to kill
//     L2-latency exposure; zero/finalize folded in (2 launches total).
// x[16384,4096] f32, w[64,4096] f32
// out: [topk_idx as f32 (2T)] [topk_weight (2T)] [aux_loss (1)]

#define T_TOKENS 16384
#define C_DIM    4096
#define E_EXP    64
#define ALPHA    0.01f

#define BT    128             // tokens per CTA
#define NTH   256             // 8 warps
#define NKS   (C_DIM / 16)    // 256 k-steps
#define NST   (NKS / 2)       // 128 stages (2 k-steps each)
#define WK    1536            // u32 per k-step of w frags
#define WK2   (2 * WK)        // u32 per stage

__device__ float g_ssum[E_EXP];
__device__ float g_cnt[E_EXP];
__device__ unsigned g_done;
// B fragments: [ks][nt][plane][lane*2+r] u32  (1.5 MB, L2-resident)
__device__ uint32_t w_frag[NKS * 8 * 3 * 64];

// exact 3-way bf16 split of (even,odd) f32 pair -> packed bf16x2 (lo=even)
__device__ __forceinline__ void split3(float fe, float fo,
                                       uint32_t& h1, uint32_t& h2, uint32_t& h3) {
    asm("cvt.rn.bf16x2.f32 %0, %1, %2;" : "=r"(h1) : "f"(fo), "f"(fe));
    float ro = fo - __uint_as_float(h1 & 0xffff0000u);
    float re = fe - __uint_as_float(h1 << 16);
    asm("cvt.rn.bf16x2.f32 %0, %1, %2;" : "=r"(h2) : "f"(ro), "f"(re));
    float so = ro - __uint_as_float(h2 & 0xffff0000u);
    float se = re - __uint_as_float(h2 << 16);
    asm("cvt.rn.bf16x2.f32 %0, %1, %2;" : "=r"(h3) : "f"(so), "f"(se));
}

#define MMA(acc, A, B)                                                        \
    asm volatile(                                                             \
        "mma.sync.aligned.m16n8k16.row.col.f32.bf16.bf16.f32 "                \
        "{%0,%1,%2,%3}, {%4,%5,%6,%7}, {%8,%9}, {%0,%1,%2,%3};"               \
        : "+f"(acc[0]), "+f"(acc[1]), "+f"(acc[2]), "+f"(acc[3])              \
        : "r"(A[0]), "r"(A[1]), "r"(A[2]), "r"(A[3]), "r"(B.x), "r"(B.y))

__device__ __forceinline__ void cp16(uint32_t sa, const void* g) {
    asm volatile("cp.async.cg.shared.global [%0], [%1], 16;" :: "r"(sa), "l"(g));
}
__device__ __forceinline__ uint32_t smem_u32(const void* p) {
    uint32_t a;
    asm("{ .reg .u64 t; cvta.to.shared.u64 t, %1; cvt.u32.u64 %0, t; }"
        : "=r"(a) : "l"(p));
    return a;
}

// Precompute w bf16x3 planes in mma B-fragment layout; also zero globals.
__global__ void prep_w(const float* __restrict__ w) {
    if (blockIdx.x == 0) {
        if (threadIdx.x < E_EXP) {
            g_ssum[threadIdx.x] = 0.f;
            g_cnt[threadIdx.x] = 0.f;
        }
        if (threadIdx.x == 64) g_done = 0;
    }
    int i = blockIdx.x * blockDim.x + threadIdx.x;   // 131072 threads
    int r = i & 1, lane = (i >> 1) & 31, nt = (i >> 6) & 7, ks = i >> 9;
    int e = nt * 8 + (lane >> 2);
    int k = ks * 16 + r * 8 + 2 * (lane & 3);
    float fe = w[(size_t)e * C_DIM + k];
    float fo = w[(size_t)e * C_DIM + k + 1];
    uint32_t h1, h2, h3;
    split3(fe, fo, h1, h2, h3);
    int base = ((ks * 8 + nt) * 3) * 64 + lane * 2 + r;
    w_frag[base]       = h1;
    w_frag[base + 64]  = h2;
    w_frag[base + 128] = h3;
}

__global__ __launch_bounds__(NTH, 1) void gate_kernel(
    const float* __restrict__ x, float* __restrict__ out)
{
    __shared__ __align__(16) uint32_t wbuf[3 * WK2];   // 36864 B, overlaid by lg
    __shared__ int s_cnt[E_EXP];
    __shared__ int s_last;
    float* lg = (float*)wbuf;                          // epilogue overlay [BT][65]

    const int tid = threadIdx.x, blk = blockIdx.x;
    const int wid = tid >> 5, lane = tid & 31;
    const int qr = lane >> 2, qc = lane & 3;
    const int trow0 = blk * BT + wid * 16 + qr;
    const float2* xr0 = (const float2*)(x + (size_t)trow0 * C_DIM) + qc;
    const float2* xr1 = (const float2*)(x + (size_t)(trow0 + 8) * C_DIM) + qc;
    const uint32_t wb_base = smem_u32(wbuf);

    if (tid < E_EXP) s_cnt[tid] = 0;

    float acc[8][4];
    #pragma unroll
    for (int nt = 0; nt < 8; nt++)
        #pragma unroll
        for (int j = 0; j < 4; j++) acc[nt][j] = 0.f;

    // cp.async one stage of w frags into slot s
    auto stage_cp = [&](int st, int slot) {
        const char* src = (const char*)(w_frag + (size_t)st * WK2) + tid * 16;
        uint32_t dst = wb_base + slot * (WK2 * 4) + tid * 16;
        #pragma unroll
        for (int p = 0; p < 3; p++)
            cp16(dst + p * 4096, src + p * 4096);
    };

    // x regs for one stage (2 k-steps): [kk][0..3]
    float2 cur[2][4], nxt[2][4];
    #pragma unroll
    for (int kk = 0; kk < 2; kk++) {
        cur[kk][0] = xr0[kk * 8];     cur[kk][1] = xr1[kk * 8];
        cur[kk][2] = xr0[kk * 8 + 4]; cur[kk][3] = xr1[kk * 8 + 4];
    }

    stage_cp(0, 0);
    asm volatile("cp.async.commit_group;");
    stage_cp(1, 1);
    asm volatile("cp.async.commit_group;");

    #pragma unroll 1
    for (int i = 0; i < NST; i++) {
        __syncthreads();                       // safe to overwrite slot (i+2)%3
        if (i + 2 < NST) stage_cp(i + 2, (i + 2) % 3);
        asm volatile("cp.async.commit_group;");
        asm volatile("cp.async.wait_group 2;");
        __syncthreads();                       // slot i%3 visible to all

        // prefetch x for next stage
        const int ni = (i + 1 < NST) ? (i + 1) : 0;
        #pragma unroll
        for (int kk = 0; kk < 2; kk++) {
            const int k8 = (2 * ni + kk) * 8;
            nxt[kk][0] = xr0[k8];     nxt[kk][1] = xr1[k8];
            nxt[kk][2] = xr0[k8 + 4]; nxt[kk][3] = xr1[k8 + 4];
        }

        const uint2* wsl = (const uint2*)(wbuf + (i % 3) * WK2);
        #pragma unroll
        for (int kk = 0; kk < 2; kk++) {
            uint32_t a1[4], a2[4], a3[4];
            split3(cur[kk][0].x, cur[kk][0].y, a1[0], a2[0], a3[0]);
            split3(cur[kk][1].x, cur[kk][1].y, a1[1], a2[1], a3[1]);
            split3(cur[kk][2].x, cur[kk][2].y, a1[2], a2[2], a3[2]);
            split3(cur[kk][3].x, cur[kk][3].y, a1[3], a2[3], a3[3]);

            const uint2* wk = wsl + kk * (WK / 2) + lane;  // +(nt*3+p)*32
            uint2 b[8];
            #pragma unroll
            for (int nt = 0; nt < 8; nt++) b[nt] = wk[nt * 96];
            #pragma unroll
            for (int nt = 0; nt < 8; nt++) MMA(acc[nt], a1, b[nt]);
            #pragma unroll
            for (int nt = 0; nt < 8; nt++) MMA(acc[nt], a2, b[nt]);
            #pragma unroll
            for (int nt = 0; nt < 8; nt++) MMA(acc[nt], a3, b[nt]);
            #pragma unroll
            for (int nt = 0; nt < 8; nt++) b[nt] = wk[nt * 96 + 32];
            #pragma unroll
            for (int nt = 0; nt < 8; nt++) MMA(acc[nt], a1, b[nt]);
            #pragma unroll
            for (int nt = 0; nt < 8; nt++) MMA(acc[nt], a2, b[nt]);
            #pragma unroll
            for (int nt = 0; nt < 8; nt++) b[nt] = wk[nt * 96 + 64];
            #pragma unroll
            for (int nt = 0; nt < 8; nt++) MMA(acc[nt], a1, b[nt]);
        }
        #pragma unroll
        for (int kk = 0; kk < 2; kk++)
            #pragma unroll
            for (int j = 0; j < 4; j++) cur[kk][j] = nxt[kk][j];
    }
    __syncthreads();    // staging done; reuse wbuf as logits

    // scatter logits: row = wid*16 + qr (+8), col = nt*8 + 2*qc (+1)
    const int lr0 = wid * 16 + qr;
    #pragma unroll
    for (int nt = 0; nt < 8; nt++) {
        const int e = nt * 8 + 2 * qc;
        lg[lr0 * 65 + e]           = acc[nt][0];
        lg[lr0 * 65 + e + 1]       = acc[nt][1];
        lg[(lr0 + 8) * 65 + e]     = acc[nt][2];
        lg[(lr0 + 8) * 65 + e + 1] = acc[nt][3];
    }
    __syncthreads();

    if (tid < BT) {
        float* row = lg + tid * 65;
        float v1 = -1e30f, v2 = -1e30f;
        int i1 = 0, i2 = 0;
        #pragma unroll
        for (int e = 0; e < E_EXP; e++) {
            float v = row[e];
            if (v > v1)      { v2 = v1; i2 = i1; v1 = v; i1 = e; }
            else if (v > v2) { v2 = v;  i2 = e; }
        }
        float Z = 0.f;
        #pragma unroll
        for (int e = 0; e < E_EXP; e++) {
            float ex = expf(row[e] - v1);
            row[e] = ex; Z += ex;
        }
        float rz = 1.0f / Z;
        #pragma unroll
        for (int e = 0; e < E_EXP; e++) row[e] *= rz;
        float s1 = row[i1], s2 = row[i2];
        float inv = 1.0f / (s1 + s2);
        int gt = blk * BT + tid;
        out[2 * gt]     = (float)i1;
        out[2 * gt + 1] = (float)i2;
        out[2 * T_TOKENS + 2 * gt]     = s1 * inv;
        out[2 * T_TOKENS + 2 * gt + 1] = s2 * inv;
        atomicAdd(&s_cnt[i1], 1);
        atomicAdd(&s_cnt[i2], 1);
    }
    __syncthreads();

    if (tid < E_EXP) {
        float sum = 0.f;
        for (int t = 0; t < BT; t++) sum += lg[t * 65 + tid];
        atomicAdd(&g_ssum[tid], sum);
        atomicAdd(&g_cnt[tid], (float)s_cnt[tid]);
    }
    __syncthreads();

    // last CTA computes aux loss
    if (tid == 0) {
        __threadfence();
        s_last = (atomicAdd(&g_done, 1u) == gridDim.x - 1);
    }
    __syncthreads();
    if (s_last) {
        if (tid < E_EXP) lg[tid] = g_ssum[tid] * g_cnt[tid];
        __syncthreads();
        if (tid == 0) {
            float s = 0.f;
            for (int e = 0; e < E_EXP; e++) s += lg[e];
            out[4 * T_TOKENS] = s * (ALPHA * (float)E_EXP /
                ((float)T_TOKENS * 2.0f * (float)T_TOKENS));
        }
    }
}

extern "C" void kernel_launch(void* const* d_in, const int* in_sizes, int n_in,
                              void* d_out, int out_size) {
    const float* x = (const float*)d_in[0];
    const float* w = (const float*)d_in[1];
    float* out = (float*)d_out;
    prep_w<<<512, 256>>>(w);
    gate_kernel<<<T_TOKENS / BT, NTH>>>(x, out);
}

// round 5
// speedup vs baseline: 1.3645x; 1.1457x over previous
#include <cuda_runtime.h>
#include <math.h>
#include <stdint.h>

// SparseMoEGate via mma.sync (HMMA) fp16x2 exact-split GEMM (3 MMAs/k-step).
// w pre-scaled by 2^14 to keep fp16 residuals normal; logits descaled by 2^-14.
// x[16384,4096] f32, w[64,4096] f32
// out: [topk_idx as f32 (2T)] [topk_weight (2T)] [aux_loss (1)]

#define T_TOKENS 16384
#define C_DIM    4096
#define E_EXP    64
#define ALPHA    0.01f
#define WSCALE   16384.0f
#define WDESC    6.103515625e-05f   // 2^-14

#define BT    128             // tokens per CTA
#define NTH   256             // 8 warps
#define NKS   (C_DIM / 16)    // 256 k-steps
#define NST   (NKS / 2)       // 128 stages (2 k-steps each)
#define WK    1024            // u32 per k-step of w frags (8nt x 2pl x 64)
#define WK2   (2 * WK)        // u32 per stage (8KB)

__device__ float g_ssum[E_EXP];
__device__ float g_cnt[E_EXP];
__device__ unsigned g_done;
// B fragments: [ks][nt][plane(2)][lane*2+r] u32  (1 MB, L2-resident)
__device__ uint32_t w_frag[NKS * 8 * 2 * 64];

// exact 2-way fp16 split of (even,odd) f32 pair -> 2 packed f16x2 (lo=even)
__device__ __forceinline__ void split2(float fe, float fo,
                                       uint32_t& h1, uint32_t& h2) {
    asm("cvt.rn.f16x2.f32 %0, %1, %2;" : "=r"(h1) : "f"(fo), "f"(fe));
    float ge, go;
    asm("{ .reg .f16 l, h; mov.b32 {l, h}, %2;"
        " cvt.f32.f16 %0, l; cvt.f32.f16 %1, h; }"
        : "=f"(ge), "=f"(go) : "r"(h1));
    asm("cvt.rn.f16x2.f32 %0, %1, %2;" : "=r"(h2) : "f"(fo - go), "f"(fe - ge));
}

#define MMA(acc, A, B)                                                        \
    asm volatile(                                                             \
        "mma.sync.aligned.m16n8k16.row.col.f32.f16.f16.f32 "                  \
        "{%0,%1,%2,%3}, {%4,%5,%6,%7}, {%8,%9}, {%0,%1,%2,%3};"               \
        : "+f"(acc[0]), "+f"(acc[1]), "+f"(acc[2]), "+f"(acc[3])              \
        : "r"(A[0]), "r"(A[1]), "r"(A[2]), "r"(A[3]), "r"(B.x), "r"(B.y))

__device__ __forceinline__ void cp16(uint32_t sa, const void* g) {
    asm volatile("cp.async.cg.shared.global [%0], [%1], 16;" :: "r"(sa), "l"(g));
}
__device__ __forceinline__ uint32_t smem_u32(const void* p) {
    uint32_t a;
    asm("{ .reg .u64 t; cvta.to.shared.u64 t, %1; cvt.u32.u64 %0, t; }"
        : "=r"(a) : "l"(p));
    return a;
}

// Precompute w fp16x2 planes (scaled by 2^14) in mma B-fragment layout.
__global__ void prep_w(const float* __restrict__ w) {
    if (blockIdx.x == 0) {
        if (threadIdx.x < E_EXP) {
            g_ssum[threadIdx.x] = 0.f;
            g_cnt[threadIdx.x] = 0.f;
        }
        if (threadIdx.x == 64) g_done = 0;
    }
    int i = blockIdx.x * blockDim.x + threadIdx.x;   // 131072 threads
    int r = i & 1, lane = (i >> 1) & 31, nt = (i >> 6) & 7, ks = i >> 9;
    int e = nt * 8 + (lane >> 2);
    int k = ks * 16 + r * 8 + 2 * (lane & 3);
    float fe = w[(size_t)e * C_DIM + k] * WSCALE;
    float fo = w[(size_t)e * C_DIM + k + 1] * WSCALE;
    uint32_t h1, h2;
    split2(fe, fo, h1, h2);
    int base = ((ks * 8 + nt) * 2) * 64 + lane * 2 + r;
    w_frag[base]      = h1;
    w_frag[base + 64] = h2;
}

__global__ __launch_bounds__(NTH) void gate_kernel(
    const float* __restrict__ x, float* __restrict__ out)
{
    __shared__ __align__(16) float lg[BT * 65];        // 33280 B; staging overlay
    __shared__ int s_cnt[E_EXP];
    __shared__ int s_last;
    uint32_t* wbuf = (uint32_t*)lg;                    // 3 stages x 8KB = 24KB

    const int tid = threadIdx.x, blk = blockIdx.x;
    const int wid = tid >> 5, lane = tid & 31;
    const int qr = lane >> 2, qc = lane & 3;
    const int trow0 = blk * BT + wid * 16 + qr;
    const float2* xr0 = (const float2*)(x + (size_t)trow0 * C_DIM) + qc;
    const float2* xr1 = (const float2*)(x + (size_t)(trow0 + 8) * C_DIM) + qc;
    const uint32_t wb_base = smem_u32(lg);

    if (tid < E_EXP) s_cnt[tid] = 0;

    float acc[8][4];
    #pragma unroll
    for (int nt = 0; nt < 8; nt++)
        #pragma unroll
        for (int j = 0; j < 4; j++) acc[nt][j] = 0.f;

    // cp.async one 8KB stage of w frags into slot
    auto stage_cp = [&](int st, int slot) {
        const char* src = (const char*)(w_frag + (size_t)st * WK2) + tid * 16;
        uint32_t dst = wb_base + slot * (WK2 * 4) + tid * 16;
        cp16(dst, src);
        cp16(dst + 4096, src + 4096);
    };

    // x regs for one stage (2 k-steps): [kk][0..3]
    float2 cur[2][4], nxt[2][4];
    #pragma unroll
    for (int kk = 0; kk < 2; kk++) {
        cur[kk][0] = xr0[kk * 8];     cur[kk][1] = xr1[kk * 8];
        cur[kk][2] = xr0[kk * 8 + 4]; cur[kk][3] = xr1[kk * 8 + 4];
    }

    stage_cp(0, 0);
    asm volatile("cp.async.commit_group;");
    stage_cp(1, 1);
    asm volatile("cp.async.commit_group;");

    #pragma unroll 1
    for (int i = 0; i < NST; i++) {
        __syncthreads();                       // safe to overwrite slot (i+2)%3
        if (i + 2 < NST) stage_cp(i + 2, (i + 2) % 3);
        asm volatile("cp.async.commit_group;");
        asm volatile("cp.async.wait_group 2;");
        __syncthreads();                       // slot i%3 visible

        // prefetch x for next stage
        const int ni = (i + 1 < NST) ? (i + 1) : 0;
        #pragma unroll
        for (int kk = 0; kk < 2; kk++) {
            const int k8 = (2 * ni + kk) * 8;
            nxt[kk][0] = xr0[k8];     nxt[kk][1] = xr1[k8];
            nxt[kk][2] = xr0[k8 + 4]; nxt[kk][3] = xr1[k8 + 4];
        }

        const uint2* wsl = (const uint2*)(wbuf + (i % 3) * WK2);
        #pragma unroll
        for (int kk = 0; kk < 2; kk++) {
            // split A: frag order [r0/klo, r1/klo, r0/khi, r1/khi]
            uint32_t a1[4], a2[4];
            split2(cur[kk][0].x, cur[kk][0].y, a1[0], a2[0]);
            split2(cur[kk][1].x, cur[kk][1].y, a1[1], a2[1]);
            split2(cur[kk][2].x, cur[kk][2].y, a1[2], a2[2]);
            split2(cur[kk][3].x, cur[kk][3].y, a1[3], a2[3]);

            const uint2* wk = wsl + kk * (WK / 2) + lane;  // +(nt*2+p)*32
            uint2 b1[8], b2[8];
            #pragma unroll
            for (int nt = 0; nt < 8; nt++) b1[nt] = wk[nt * 64];
            #pragma unroll
            for (int nt = 0; nt < 8; nt++) b2[nt] = wk[nt * 64 + 32];
            #pragma unroll
            for (int nt = 0; nt < 8; nt++) MMA(acc[nt], a1, b1[nt]);
            #pragma unroll
            for (int nt = 0; nt < 8; nt++) MMA(acc[nt], a2, b1[nt]);
            #pragma unroll
            for (int nt = 0; nt < 8; nt++) MMA(acc[nt], a1, b2[nt]);
        }
        #pragma unroll
        for (int kk = 0; kk < 2; kk++)
            #pragma unroll
            for (int j = 0; j < 4; j++) cur[kk][j] = nxt[kk][j];
    }
    __syncthreads();    // staging done; reuse lg as logits

    // scatter logits (descaled): row = wid*16 + qr (+8), col = nt*8 + 2*qc (+1)
    const int lr0 = wid * 16 + qr;
    #pragma unroll
    for (int nt = 0; nt < 8; nt++) {
        const int e = nt * 8 + 2 * qc;
        lg[lr0 * 65 + e]           = acc[nt][0] * WDESC;
        lg[lr0 * 65 + e + 1]       = acc[nt][1] * WDESC;
        lg[(lr0 + 8) * 65 + e]     = acc[nt][2] * WDESC;
        lg[(lr0 + 8) * 65 + e + 1] = acc[nt][3] * WDESC;
    }
    __syncthreads();

    if (tid < BT) {
        float* row = lg + tid * 65;
        float v1 = -1e30f, v2 = -1e30f;
        int i1 = 0, i2 = 0;
        #pragma unroll
        for (int e = 0; e < E_EXP; e++) {
            float v = row[e];
            if (v > v1)      { v2 = v1; i2 = i1; v1 = v; i1 = e; }
            else if (v > v2) { v2 = v;  i2 = e; }
        }
        float Z = 0.f;
        #pragma unroll
        for (int e = 0; e < E_EXP; e++) {
            float ex = expf(row[e] - v1);
            row[e] = ex; Z += ex;
        }
        float rz = 1.0f / Z;
        #pragma unroll
        for (int e = 0; e < E_EXP; e++) row[e] *= rz;
        float s1 = row[i1], s2 = row[i2];
        float inv = 1.0f / (s1 + s2);
        int gt = blk * BT + tid;
        out[2 * gt]     = (float)i1;
        out[2 * gt + 1] = (float)i2;
        out[2 * T_TOKENS + 2 * gt]     = s1 * inv;
        out[2 * T_TOKENS + 2 * gt + 1] = s2 * inv;
        atomicAdd(&s_cnt[i1], 1);
        atomicAdd(&s_cnt[i2], 1);
    }
    __syncthreads();

    if (tid < E_EXP) {
        float sum = 0.f;
        for (int t = 0; t < BT; t++) sum += lg[t * 65 + tid];
        atomicAdd(&g_ssum[tid], sum);
        atomicAdd(&g_cnt[tid], (float)s_cnt[tid]);
    }
    __syncthreads();

    // last CTA computes aux loss
    if (tid == 0) {
        __threadfence();
        s_last = (atomicAdd(&g_done, 1u) == gridDim.x - 1);
    }
    __syncthreads();
    if (s_last) {
        if (tid < E_EXP) lg[tid] = g_ssum[tid] * g_cnt[tid];
        __syncthreads();
        if (tid == 0) {
            float s = 0.f;
            for (int e = 0; e < E_EXP; e++) s += lg[e];
            out[4 * T_TOKENS] = s * (ALPHA * (float)E_EXP /
                ((float)T_TOKENS * 2.0f * (float)T_TOKENS));
        }
    }
}

extern "C" void kernel_launch(void* const* d_in, const int* in_sizes, int n_in,
                              void* d_out, int out_size) {
    const float* x = (const float*)d_in[0];
    const float* w = (const float*)d_in[1];
    float* out = (float*)d_out;
    prep_w<<<512, 256>>>(w);
    gate_kernel<<<T_TOKENS / BT, NTH>>>(x, out);
}

// round 6
// speedup vs baseline: 1.3904x; 1.0190x over previous
#include <cuda_runtime.h>
#include <math.h>
#include <stdint.h>

// SparseMoEGate via mma.sync (HMMA) fp16x2 exact-split GEMM (3 MMAs/k-step).
// R6: 16 warps/CTA, each warp 16 tokens x 32 experts -> 4 warps/SMSP.
// x[16384,4096] f32, w[64,4096] f32
// out: [topk_idx as f32 (2T)] [topk_weight (2T)] [aux_loss (1)]

#define T_TOKENS 16384
#define C_DIM    4096
#define E_EXP    64
#define ALPHA    0.01f
#define WSCALE   16384.0f
#define WDESC    6.103515625e-05f   // 2^-14

#define BT    128             // tokens per CTA
#define NTH   512             // 16 warps
#define NKS   (C_DIM / 16)    // 256 k-steps
#define NST   (NKS / 2)       // 128 stages (2 k-steps each)
#define WK    1024            // u32 per k-step of w frags (8nt x 2pl x 64)
#define WK2   (2 * WK)        // u32 per stage (8KB)

__device__ float g_ssum[E_EXP];
__device__ float g_cnt[E_EXP];
__device__ unsigned g_done;
// B fragments: [ks][nt][plane(2)][lane*2+r] u32  (1 MB, L2-resident)
__device__ uint32_t w_frag[NKS * 8 * 2 * 64];

// exact 2-way fp16 split of (even,odd) f32 pair -> 2 packed f16x2 (lo=even)
__device__ __forceinline__ void split2(float fe, float fo,
                                       uint32_t& h1, uint32_t& h2) {
    asm("cvt.rn.f16x2.f32 %0, %1, %2;" : "=r"(h1) : "f"(fo), "f"(fe));
    float ge, go;
    asm("{ .reg .f16 l, h; mov.b32 {l, h}, %2;"
        " cvt.f32.f16 %0, l; cvt.f32.f16 %1, h; }"
        : "=f"(ge), "=f"(go) : "r"(h1));
    asm("cvt.rn.f16x2.f32 %0, %1, %2;" : "=r"(h2) : "f"(fo - go), "f"(fe - ge));
}

#define MMA(acc, A, B)                                                        \
    asm volatile(                                                             \
        "mma.sync.aligned.m16n8k16.row.col.f32.f16.f16.f32 "                  \
        "{%0,%1,%2,%3}, {%4,%5,%6,%7}, {%8,%9}, {%0,%1,%2,%3};"               \
        : "+f"(acc[0]), "+f"(acc[1]), "+f"(acc[2]), "+f"(acc[3])              \
        : "r"(A[0]), "r"(A[1]), "r"(A[2]), "r"(A[3]), "r"(B.x), "r"(B.y))

__device__ __forceinline__ void cp16(uint32_t sa, const void* g) {
    asm volatile("cp.async.cg.shared.global [%0], [%1], 16;" :: "r"(sa), "l"(g));
}
__device__ __forceinline__ uint32_t smem_u32(const void* p) {
    uint32_t a;
    asm("{ .reg .u64 t; cvta.to.shared.u64 t, %1; cvt.u32.u64 %0, t; }"
        : "=r"(a) : "l"(p));
    return a;
}

// Precompute w fp16x2 planes (scaled by 2^14) in mma B-fragment layout.
__global__ void prep_w(const float* __restrict__ w) {
    if (blockIdx.x == 0) {
        if (threadIdx.x < E_EXP) {
            g_ssum[threadIdx.x] = 0.f;
            g_cnt[threadIdx.x] = 0.f;
        }
        if (threadIdx.x == 64) g_done = 0;
    }
    int i = blockIdx.x * blockDim.x + threadIdx.x;   // 131072 threads
    int r = i & 1, lane = (i >> 1) & 31, nt = (i >> 6) & 7, ks = i >> 9;
    int e = nt * 8 + (lane >> 2);
    int k = ks * 16 + r * 8 + 2 * (lane & 3);
    float fe = w[(size_t)e * C_DIM + k] * WSCALE;
    float fo = w[(size_t)e * C_DIM + k + 1] * WSCALE;
    uint32_t h1, h2;
    split2(fe, fo, h1, h2);
    int base = ((ks * 8 + nt) * 2) * 64 + lane * 2 + r;
    w_frag[base]      = h1;
    w_frag[base + 64] = h2;
}

__global__ __launch_bounds__(NTH) void gate_kernel(
    const float* __restrict__ x, float* __restrict__ out)
{
    __shared__ __align__(16) float lg[BT * 65];        // 33280 B; staging overlay
    __shared__ int s_cnt[E_EXP];
    __shared__ int s_last;
    uint32_t* wbuf = (uint32_t*)lg;                    // 3 stages x 8KB = 24KB

    const int tid = threadIdx.x, blk = blockIdx.x;
    const int wid = tid >> 5, lane = tid & 31;
    const int tg = wid & 7;          // token group (16 tokens)
    const int nh = wid >> 3;         // expert half (32 experts)
    const int qr = lane >> 2, qc = lane & 3;
    const int trow0 = blk * BT + tg * 16 + qr;
    const float2* xr0 = (const float2*)(x + (size_t)trow0 * C_DIM) + qc;
    const float2* xr1 = (const float2*)(x + (size_t)(trow0 + 8) * C_DIM) + qc;
    const uint32_t wb_base = smem_u32(lg);

    if (tid < E_EXP) s_cnt[tid] = 0;

    float acc[4][4];
    #pragma unroll
    for (int j = 0; j < 4; j++)
        #pragma unroll
        for (int q = 0; q < 4; q++) acc[j][q] = 0.f;

    // cp.async one 8KB stage of w frags into slot (512 thr x 16B)
    auto stage_cp = [&](int st, int slot) {
        const char* src = (const char*)(w_frag + (size_t)st * WK2) + tid * 16;
        uint32_t dst = wb_base + slot * (WK2 * 4) + tid * 16;
        cp16(dst, src);
    };

    // x regs for one stage (2 k-steps): [kk][0..3]
    float2 cur[2][4], nxt[2][4];
    #pragma unroll
    for (int kk = 0; kk < 2; kk++) {
        cur[kk][0] = xr0[kk * 8];     cur[kk][1] = xr1[kk * 8];
        cur[kk][2] = xr0[kk * 8 + 4]; cur[kk][3] = xr1[kk * 8 + 4];
    }

    stage_cp(0, 0);
    asm volatile("cp.async.commit_group;");
    stage_cp(1, 1);
    asm volatile("cp.async.commit_group;");

    #pragma unroll 1
    for (int i = 0; i < NST; i++) {
        __syncthreads();                       // safe to overwrite slot (i+2)%3
        if (i + 2 < NST) stage_cp(i + 2, (i + 2) % 3);
        asm volatile("cp.async.commit_group;");
        asm volatile("cp.async.wait_group 2;");
        __syncthreads();                       // slot i%3 visible

        // prefetch x for next stage
        const int ni = (i + 1 < NST) ? (i + 1) : 0;
        #pragma unroll
        for (int kk = 0; kk < 2; kk++) {
            const int k8 = (2 * ni + kk) * 8;
            nxt[kk][0] = xr0[k8];     nxt[kk][1] = xr1[k8];
            nxt[kk][2] = xr0[k8 + 4]; nxt[kk][3] = xr1[k8 + 4];
        }

        const uint2* wsl = (const uint2*)(wbuf + (i % 3) * WK2);
        #pragma unroll
        for (int kk = 0; kk < 2; kk++) {
            // split A: frag order [r0/klo, r1/klo, r0/khi, r1/khi]
            uint32_t a1[4], a2[4];
            split2(cur[kk][0].x, cur[kk][0].y, a1[0], a2[0]);
            split2(cur[kk][1].x, cur[kk][1].y, a1[1], a2[1]);
            split2(cur[kk][2].x, cur[kk][2].y, a1[2], a2[2]);
            split2(cur[kk][3].x, cur[kk][3].y, a1[3], a2[3]);

            // b-frags for this warp's 4 n-tiles: +((nh*4+j)*2+pl)*32
            const uint2* wk = wsl + kk * (WK / 2) + nh * 256 + lane;
            uint2 b1[4], b2[4];
            #pragma unroll
            for (int j = 0; j < 4; j++) b1[j] = wk[j * 64];
            #pragma unroll
            for (int j = 0; j < 4; j++) b2[j] = wk[j * 64 + 32];
            #pragma unroll
            for (int j = 0; j < 4; j++) MMA(acc[j], a1, b1[j]);
            #pragma unroll
            for (int j = 0; j < 4; j++) MMA(acc[j], a2, b1[j]);
            #pragma unroll
            for (int j = 0; j < 4; j++) MMA(acc[j], a1, b2[j]);
        }
        #pragma unroll
        for (int kk = 0; kk < 2; kk++)
            #pragma unroll
            for (int q = 0; q < 4; q++) cur[kk][q] = nxt[kk][q];
    }
    __syncthreads();    // staging done; reuse lg as logits

    // scatter logits (descaled): row = tg*16 + qr (+8), col = (nh*4+j)*8 + 2*qc
    const int lr0 = tg * 16 + qr;
    #pragma unroll
    for (int j = 0; j < 4; j++) {
        const int e = (nh * 4 + j) * 8 + 2 * qc;
        lg[lr0 * 65 + e]           = acc[j][0] * WDESC;
        lg[lr0 * 65 + e + 1]       = acc[j][1] * WDESC;
        lg[(lr0 + 8) * 65 + e]     = acc[j][2] * WDESC;
        lg[(lr0 + 8) * 65 + e + 1] = acc[j][3] * WDESC;
    }
    __syncthreads();

    if (tid < BT) {
        float* row = lg + tid * 65;
        float v1 = -1e30f, v2 = -1e30f;
        int i1 = 0, i2 = 0;
        #pragma unroll
        for (int e = 0; e < E_EXP; e++) {
            float v = row[e];
            if (v > v1)      { v2 = v1; i2 = i1; v1 = v; i1 = e; }
            else if (v > v2) { v2 = v;  i2 = e; }
        }
        float Z = 0.f;
        #pragma unroll
        for (int e = 0; e < E_EXP; e++) {
            float ex = expf(row[e] - v1);
            row[e] = ex; Z += ex;
        }
        float rz = 1.0f / Z;
        #pragma unroll
        for (int e = 0; e < E_EXP; e++) row[e] *= rz;
        float s1 = row[i1], s2 = row[i2];
        float inv = 1.0f / (s1 + s2);
        int gt = blk * BT + tid;
        out[2 * gt]     = (float)i1;
        out[2 * gt + 1] = (float)i2;
        out[2 * T_TOKENS + 2 * gt]     = s1 * inv;
        out[2 * T_TOKENS + 2 * gt + 1] = s2 * inv;
        atomicAdd(&s_cnt[i1], 1);
        atomicAdd(&s_cnt[i2], 1);
    }
    __syncthreads();

    if (tid < E_EXP) {
        float sum = 0.f;
        for (int t = 0; t < BT; t++) sum += lg[t * 65 + tid];
        atomicAdd(&g_ssum[tid], sum);
        atomicAdd(&g_cnt[tid], (float)s_cnt[tid]);
    }
    __syncthreads();

    // last CTA computes aux loss
    if (tid == 0) {
        __threadfence();
        s_last = (atomicAdd(&g_done, 1u) == gridDim.x - 1);
    }
    __syncthreads();
    if (s_last) {
        if (tid < E_EXP) lg[tid] = g_ssum[tid] * g_cnt[tid];
        __syncthreads();
        if (tid == 0) {
            float s = 0.f;
            for (int e = 0; e < E_EXP; e++) s += lg[e];
            out[4 * T_TOKENS] = s * (ALPHA * (float)E_EXP /
                ((float)T_TOKENS * 2.0f * (float)T_TOKENS));
        }
    }
}

extern "C" void kernel_launch(void* const* d_in, const int* in_sizes, int n_in,
                              void* d_out, int out_size) {
    const float* x = (const float*)d_in[0];
    const float* w = (const float*)d_in[1];
    float* out = (float*)d_out;
    prep_w<<<512, 256>>>(w);
    gate_kernel<<<T_TOKENS / BT, NTH>>>(x, out);
}

// round 9
// speedup vs baseline: 1.8331x; 1.3184x over previous
#include <cuda_runtime.h>
#include <math.h>
#include <stdint.h>

// SparseMoEGate via mma.sync (HMMA) fp16x2 exact-split GEMM (3 MMAs/k-step).
// R9 = R8 with the token-row indexing fix (tg*16 + qr) in the compute loop.
// x staged through smem via coalesced cp.async; 4-slot ring, 1 barrier/stage.
// x[16384,4096] f32, w[64,4096] f32
// out: [topk_idx as f32 (2T)] [topk_weight (2T)] [aux_loss (1)]

#define T_TOKENS 16384
#define C_DIM    4096
#define E_EXP    64
#define ALPHA    0.01f
#define WSCALE   16384.0f
#define WDESC    6.103515625e-05f   // 2^-14

#define BT    128             // tokens per CTA
#define NTH   512             // 16 warps
#define NKS   (C_DIM / 16)    // 256 k-steps
#define NST   (NKS / 2)       // 128 stages (2 k-steps each)
#define WK    1024            // u32 per k-step of w frags
#define WK2   (2 * WK)        // u32 per stage (8KB)

#define XROW  144             // bytes per x row in smem (36 floats, bank-optimal)
#define XOFF_W 18432          // w frags after 128*144 B of x
#define SLOT  26624           // stage slot bytes (x 18432 + w 8192)
#define SMEM_BYTES (4 * SLOT) // 106496

__device__ float g_ssum[E_EXP];
__device__ float g_cnt[E_EXP];
__device__ unsigned g_done;
// B fragments: [ks][nt][plane(2)][lane*2+r] u32  (1 MB, L2-resident)
__device__ uint32_t w_frag[NKS * 8 * 2 * 64];

// exact 2-way fp16 split of (even,odd) f32 pair -> 2 packed f16x2 (lo=even)
__device__ __forceinline__ void split2v(float fe, float fo,
                                        uint32_t& h1, uint32_t& h2) {
    asm("cvt.rn.f16x2.f32 %0, %1, %2;" : "=r"(h1) : "f"(fo), "f"(fe));
    float ge, go;
    asm("{ .reg .f16 l, h; mov.b32 {l, h}, %2;"
        " cvt.f32.f16 %0, l; cvt.f32.f16 %1, h; }"
        : "=f"(ge), "=f"(go) : "r"(h1));
    asm("cvt.rn.f16x2.f32 %0, %1, %2;" : "=r"(h2) : "f"(fo - go), "f"(fe - ge));
}

#define MMA(acc, A, B)                                                        \
    asm volatile(                                                             \
        "mma.sync.aligned.m16n8k16.row.col.f32.f16.f16.f32 "                  \
        "{%0,%1,%2,%3}, {%4,%5,%6,%7}, {%8,%9}, {%0,%1,%2,%3};"               \
        : "+f"(acc[0]), "+f"(acc[1]), "+f"(acc[2]), "+f"(acc[3])              \
        : "r"(A[0]), "r"(A[1]), "r"(A[2]), "r"(A[3]), "r"(B.x), "r"(B.y))

__device__ __forceinline__ void cp16(uint32_t sa, const void* g) {
    asm volatile("cp.async.cg.shared.global [%0], [%1], 16;" :: "r"(sa), "l"(g));
}
__device__ __forceinline__ uint32_t smem_u32(const void* p) {
    uint32_t a;
    asm("{ .reg .u64 t; cvta.to.shared.u64 t, %1; cvt.u32.u64 %0, t; }"
        : "=r"(a) : "l"(p));
    return a;
}

// Precompute w fp16x2 planes (scaled by 2^14) in mma B-fragment layout.
__global__ void prep_w(const float* __restrict__ w) {
    if (blockIdx.x == 0) {
        if (threadIdx.x < E_EXP) {
            g_ssum[threadIdx.x] = 0.f;
            g_cnt[threadIdx.x] = 0.f;
        }
        if (threadIdx.x == 64) g_done = 0;
    }
    int i = blockIdx.x * blockDim.x + threadIdx.x;   // 131072 threads
    int r = i & 1, lane = (i >> 1) & 31, nt = (i >> 6) & 7, ks = i >> 9;
    int e = nt * 8 + (lane >> 2);
    int k = ks * 16 + r * 8 + 2 * (lane & 3);
    float fe = w[(size_t)e * C_DIM + k] * WSCALE;
    float fo = w[(size_t)e * C_DIM + k + 1] * WSCALE;
    uint32_t h1, h2;
    split2v(fe, fo, h1, h2);
    int base = ((ks * 8 + nt) * 2) * 64 + lane * 2 + r;
    w_frag[base]      = h1;
    w_frag[base + 64] = h2;
}

extern __shared__ __align__(16) char dsm[];

__global__ __launch_bounds__(NTH) void gate_kernel(
    const float* __restrict__ x, float* __restrict__ out)
{
    __shared__ int s_cnt[E_EXP];
    __shared__ int s_last;
    float* lg = (float*)dsm;                 // epilogue overlay [BT][65]

    const int tid = threadIdx.x, blk = blockIdx.x;
    const int wid = tid >> 5, lane = tid & 31;
    const int tg = wid & 7;                  // token group (16 tokens)
    const int nh = wid >> 3;                 // expert half (32 experts)
    const int qr = lane >> 2, qc = lane & 3;
    const uint32_t sb = smem_u32(dsm);

    // this warp's token rows within the smem x tile
    const int xr_lo = tg * 16 + qr;          // rows 0..127
    const int xr_hi = xr_lo + 8;

    // cp geometry: x rows split 512 thr -> 64 rows x 8 segs, 2 iterations
    const int crow = tid >> 3, cseg = tid & 7;
    const float* xg = x + (size_t)(blk * BT + crow) * C_DIM + cseg * 4;

    if (tid < E_EXP) s_cnt[tid] = 0;

    float acc[4][4];
    #pragma unroll
    for (int j = 0; j < 4; j++)
        #pragma unroll
        for (int q = 0; q < 4; q++) acc[j][q] = 0.f;

    auto stage_cp = [&](int st, int slot) {
        const uint32_t base = sb + slot * SLOT;
        // x: 128 rows x 128B, coalesced, padded rows (144B pitch)
        cp16(base + crow * XROW + cseg * 16, xg + st * 32);
        cp16(base + (crow + 64) * XROW + cseg * 16,
             xg + (size_t)64 * C_DIM + st * 32);
        // w frags: 8KB
        cp16(base + XOFF_W + tid * 16,
             (const char*)(w_frag + (size_t)st * WK2) + tid * 16);
    };

    stage_cp(0, 0); asm volatile("cp.async.commit_group;");
    stage_cp(1, 1); asm volatile("cp.async.commit_group;");
    stage_cp(2, 2); asm volatile("cp.async.commit_group;");

    #pragma unroll 1
    for (int i = 0; i < NST; i++) {
        asm volatile("cp.async.wait_group 2;");
        __syncthreads();                     // stage i visible; slot (i+3)%4 free

        if (i + 3 < NST) stage_cp(i + 3, (i + 3) & 3);
        asm volatile("cp.async.commit_group;");

        const char* xs = dsm + (i & 3) * SLOT;
        const uint2* ws = (const uint2*)(xs + XOFF_W);

        #pragma unroll
        for (int kk = 0; kk < 2; kk++) {
            float2 x0 = *(const float2*)(xs + xr_lo * XROW + kk * 64 + qc * 8);
            float2 x1 = *(const float2*)(xs + xr_hi * XROW + kk * 64 + qc * 8);
            float2 x2 = *(const float2*)(xs + xr_lo * XROW + kk * 64 + 32 + qc * 8);
            float2 x3 = *(const float2*)(xs + xr_hi * XROW + kk * 64 + 32 + qc * 8);

            // A frag order [r0/klo, r1/klo, r0/khi, r1/khi]
            uint32_t a1[4], a2[4];
            split2v(x0.x, x0.y, a1[0], a2[0]);
            split2v(x1.x, x1.y, a1[1], a2[1]);
            split2v(x2.x, x2.y, a1[2], a2[2]);
            split2v(x3.x, x3.y, a1[3], a2[3]);

            const uint2* wk = ws + kk * 512 + nh * 256 + lane;
            uint2 b1[4], b2[4];
            #pragma unroll
            for (int j = 0; j < 4; j++) b1[j] = wk[j * 64];
            #pragma unroll
            for (int j = 0; j < 4; j++) b2[j] = wk[j * 64 + 32];
            #pragma unroll
            for (int j = 0; j < 4; j++) MMA(acc[j], a1, b1[j]);
            #pragma unroll
            for (int j = 0; j < 4; j++) MMA(acc[j], a2, b1[j]);
            #pragma unroll
            for (int j = 0; j < 4; j++) MMA(acc[j], a1, b2[j]);
        }
    }
    __syncthreads();    // staging done; reuse dsm as logits

    // scatter logits (descaled): row = tg*16 + qr (+8), col = (nh*4+j)*8 + 2*qc
    const int lr0 = tg * 16 + qr;
    #pragma unroll
    for (int j = 0; j < 4; j++) {
        const int e = (nh * 4 + j) * 8 + 2 * qc;
        lg[lr0 * 65 + e]           = acc[j][0] * WDESC;
        lg[lr0 * 65 + e + 1]       = acc[j][1] * WDESC;
        lg[(lr0 + 8) * 65 + e]     = acc[j][2] * WDESC;
        lg[(lr0 + 8) * 65 + e + 1] = acc[j][3] * WDESC;
    }
    __syncthreads();

    if (tid < BT) {
        float* row = lg + tid * 65;
        float v1 = -1e30f, v2 = -1e30f;
        int i1 = 0, i2 = 0;
        #pragma unroll
        for (int e = 0; e < E_EXP; e++) {
            float v = row[e];
            if (v > v1)      { v2 = v1; i2 = i1; v1 = v; i1 = e; }
            else if (v > v2) { v2 = v;  i2 = e; }
        }
        float Z = 0.f;
        #pragma unroll
        for (int e = 0; e < E_EXP; e++) {
            float ex = expf(row[e] - v1);
            row[e] = ex; Z += ex;
        }
        float rz = 1.0f / Z;
        #pragma unroll
        for (int e = 0; e < E_EXP; e++) row[e] *= rz;
        float s1 = row[i1], s2 = row[i2];
        float inv = 1.0f / (s1 + s2);
        int gt = blk * BT + tid;
        out[2 * gt]     = (float)i1;
        out[2 * gt + 1] = (float)i2;
        out[2 * T_TOKENS + 2 * gt]     = s1 * inv;
        out[2 * T_TOKENS + 2 * gt + 1] = s2 * inv;
        atomicAdd(&s_cnt[i1], 1);
        atomicAdd(&s_cnt[i2], 1);
    }
    __syncthreads();

    if (tid < E_EXP) {
        float sum = 0.f;
        for (int t = 0; t < BT; t++) sum += lg[t * 65 + tid];
        atomicAdd(&g_ssum[tid], sum);
        atomicAdd(&g_cnt[tid], (float)s_cnt[tid]);
    }
    __syncthreads();

    // last CTA computes aux loss
    if (tid == 0) {
        __threadfence();
        s_last = (atomicAdd(&g_done, 1u) == gridDim.x - 1);
    }
    __syncthreads();
    if (s_last) {
        if (tid < E_EXP) lg[tid] = g_ssum[tid] * g_cnt[tid];
        __syncthreads();
        if (tid == 0) {
            float s = 0.f;
            for (int e = 0; e < E_EXP; e++) s += lg[e];
            out[4 * T_TOKENS] = s * (ALPHA * (float)E_EXP /
                ((float)T_TOKENS * 2.0f * (float)T_TOKENS));
        }
    }
}

extern "C" void kernel_launch(void* const* d_in, const int* in_sizes, int n_in,
                              void* d_out, int out_size) {
    const float* x = (const float*)d_in[0];
    const float* w = (const float*)d_in[1];
    float* out = (float*)d_out;
    cudaFuncSetAttribute(gate_kernel,
                         cudaFuncAttributeMaxDynamicSharedMemorySize, SMEM_BYTES);
    prep_w<<<512, 256>>>(w);
    gate_kernel<<<T_TOKENS / BT, NTH, SMEM_BYTES>>>(x, out);
}

// round 10
// speedup vs baseline: 1.9618x; 1.0702x over previous
#include <cuda_runtime.h>
#include <math.h>
#include <stdint.h>

// SparseMoEGate via mma.sync (HMMA) fp16x2 exact-split GEMM (3 MMAs/k-step).
// R10: 4-kstep stages (3 slots, 64 barriers) + ldmatrix.x4 for w fragments.
// x[16384,4096] f32, w[64,4096] f32
// out: [topk_idx as f32 (2T)] [topk_weight (2T)] [aux_loss (1)]

#define T_TOKENS 16384
#define C_DIM    4096
#define E_EXP    64
#define ALPHA    0.01f
#define WSCALE   16384.0f
#define WDESC    6.103515625e-05f   // 2^-14

#define BT    128             // tokens per CTA
#define NTH   512             // 16 warps
#define NKS   (C_DIM / 16)    // 256 k-steps
#define KPS   4               // k-steps per stage
#define NST   (NKS / KPS)     // 64 stages

#define XROW  272             // bytes per x row in smem (256B data + 16B pad)
#define XOFF_W 34816          // 128 * 272
#define WSTG  16384           // w bytes per stage (4 ksteps x 4KB)
#define SLOT  (XOFF_W + WSTG) // 51200
#define SMEM_BYTES (3 * SLOT) // 153600

__device__ float g_ssum[E_EXP];
__device__ float g_cnt[E_EXP];
__device__ unsigned g_done;
// B tiles, ldmatrix layout: [ks][nt][pl][t][n-row] 16B rows  (1 MB)
__device__ __align__(16) uint32_t w_frag[NKS * 1024];

// exact 2-way fp16 split of (even,odd) f32 pair -> 2 packed f16x2 (lo=even)
__device__ __forceinline__ void split2v(float fe, float fo,
                                        uint32_t& h1, uint32_t& h2) {
    asm("cvt.rn.f16x2.f32 %0, %1, %2;" : "=r"(h1) : "f"(fo), "f"(fe));
    float ge, go;
    asm("{ .reg .f16 l, h; mov.b32 {l, h}, %2;"
        " cvt.f32.f16 %0, l; cvt.f32.f16 %1, h; }"
        : "=f"(ge), "=f"(go) : "r"(h1));
    asm("cvt.rn.f16x2.f32 %0, %1, %2;" : "=r"(h2) : "f"(fo - go), "f"(fe - ge));
}

#define MMA(acc, A, B)                                                        \
    asm volatile(                                                             \
        "mma.sync.aligned.m16n8k16.row.col.f32.f16.f16.f32 "                  \
        "{%0,%1,%2,%3}, {%4,%5,%6,%7}, {%8,%9}, {%0,%1,%2,%3};"               \
        : "+f"(acc[0]), "+f"(acc[1]), "+f"(acc[2]), "+f"(acc[3])              \
        : "r"(A[0]), "r"(A[1]), "r"(A[2]), "r"(A[3]), "r"(B.x), "r"(B.y))

#define LDMX4(r0, r1, r2, r3, a)                                              \
    asm volatile("ldmatrix.sync.aligned.m8n8.x4.shared.b16 {%0,%1,%2,%3}, [%4];" \
        : "=r"(r0), "=r"(r1), "=r"(r2), "=r"(r3) : "r"(a))

__device__ __forceinline__ void cp16(uint32_t sa, const void* g) {
    asm volatile("cp.async.cg.shared.global [%0], [%1], 16;" :: "r"(sa), "l"(g));
}
__device__ __forceinline__ uint32_t smem_u32(const void* p) {
    uint32_t a;
    asm("{ .reg .u64 t; cvta.to.shared.u64 t, %1; cvt.u32.u64 %0, t; }"
        : "=r"(a) : "l"(p));
    return a;
}

// Precompute w fp16x2 planes (scaled by 2^14) in ldmatrix tile layout.
// thread i -> (ks, e, t): computes one 16B row per plane.
__global__ void prep_w(const float* __restrict__ w) {
    if (blockIdx.x == 0) {
        if (threadIdx.x < E_EXP) {
            g_ssum[threadIdx.x] = 0.f;
            g_cnt[threadIdx.x] = 0.f;
        }
        if (threadIdx.x == 64) g_done = 0;
    }
    int i = blockIdx.x * blockDim.x + threadIdx.x;   // 32768 threads
    int t = i & 1, e = (i >> 1) & 63, ks = i >> 7;
    const float* src = w + (size_t)e * C_DIM + ks * 16 + t * 8;
    uint32_t h1[4], h2[4];
    #pragma unroll
    for (int p = 0; p < 4; p++)
        split2v(src[2 * p] * WSCALE, src[2 * p + 1] * WSCALE, h1[p], h2[p]);
    int nt = e >> 3, n = e & 7;
    char* base = (char*)w_frag + (size_t)ks * 4096 + nt * 512 + t * 128 + n * 16;
    *(uint4*)(base)       = make_uint4(h1[0], h1[1], h1[2], h1[3]);  // plane 1
    *(uint4*)(base + 256) = make_uint4(h2[0], h2[1], h2[2], h2[3]);  // plane 2
}

extern __shared__ __align__(16) char dsm[];

__global__ __launch_bounds__(NTH) void gate_kernel(
    const float* __restrict__ x, float* __restrict__ out)
{
    __shared__ int s_cnt[E_EXP];
    __shared__ int s_last;
    float* lg = (float*)dsm;                 // epilogue overlay [BT][65]

    const int tid = threadIdx.x, blk = blockIdx.x;
    const int wid = tid >> 5, lane = tid & 31;
    const int tg = wid & 7;                  // token group (16 tokens)
    const int nh = wid >> 3;                 // expert half (32 experts)
    const int qr = lane >> 2, qc = lane & 3;
    const uint32_t sb = smem_u32(dsm);

    const int xr_lo = tg * 16 + qr;
    const int xr_hi = xr_lo + 8;
    // per-lane ldmatrix address part: 4 tiles -> lane groups of 8
    const uint32_t wlane = (nh * 4) * 512 + ((lane >> 3) * 128) + ((lane & 7) * 16);

    // cp geometry: x rows 512 thr -> 64 rows x 8 segs(16B)
    const int crow = tid >> 3, cseg = tid & 7;
    const float* xg = x + (size_t)(blk * BT + crow) * C_DIM + cseg * 4;

    if (tid < E_EXP) s_cnt[tid] = 0;

    float acc[4][4];
    #pragma unroll
    for (int j = 0; j < 4; j++)
        #pragma unroll
        for (int q = 0; q < 4; q++) acc[j][q] = 0.f;

    auto stage_cp = [&](int st, int slot) {
        const uint32_t base = sb + slot * SLOT;
        // x: 128 rows x 256B, coalesced 128B runs, 272B pitch
        #pragma unroll
        for (int rh = 0; rh < 2; rh++)
            #pragma unroll
            for (int kh = 0; kh < 2; kh++)
                cp16(base + (crow + rh * 64) * XROW + kh * 128 + cseg * 16,
                     xg + (size_t)(rh * 64) * C_DIM + st * 64 + kh * 32);
        // w tiles: 16KB contiguous
        const char* wsrc = (const char*)w_frag + (size_t)st * WSTG + tid * 16;
        cp16(base + XOFF_W + tid * 16, wsrc);
        cp16(base + XOFF_W + 8192 + tid * 16, wsrc + 8192);
    };

    stage_cp(0, 0); asm volatile("cp.async.commit_group;");
    stage_cp(1, 1); asm volatile("cp.async.commit_group;");

    #pragma unroll 1
    for (int i = 0; i < NST; i++) {
        asm volatile("cp.async.wait_group 1;");
        __syncthreads();                     // stage i visible; slot (i+2)%3 free

        if (i + 2 < NST) stage_cp(i + 2, (i + 2) % 3);
        asm volatile("cp.async.commit_group;");

        const char* xs = dsm + (i % 3) * SLOT;
        const uint32_t wbase = sb + (i % 3) * SLOT + XOFF_W + wlane;

        #pragma unroll
        for (int kk = 0; kk < KPS; kk++) {
            float2 x0 = *(const float2*)(xs + xr_lo * XROW + kk * 64 + qc * 8);
            float2 x1 = *(const float2*)(xs + xr_hi * XROW + kk * 64 + qc * 8);
            float2 x2 = *(const float2*)(xs + xr_lo * XROW + kk * 64 + 32 + qc * 8);
            float2 x3 = *(const float2*)(xs + xr_hi * XROW + kk * 64 + 32 + qc * 8);

            // A frag order [r0/klo, r1/klo, r0/khi, r1/khi]
            uint32_t a1[4], a2[4];
            split2v(x0.x, x0.y, a1[0], a2[0]);
            split2v(x1.x, x1.y, a1[1], a2[1]);
            split2v(x2.x, x2.y, a1[2], a2[2]);
            split2v(x3.x, x3.y, a1[3], a2[3]);

            uint2 b1[4], b2[4];
            #pragma unroll
            for (int j = 0; j < 4; j++) {
                uint32_t r0, r1, r2, r3;
                LDMX4(r0, r1, r2, r3, wbase + kk * 4096 + j * 512);
                b1[j].x = r0; b1[j].y = r1;
                b2[j].x = r2; b2[j].y = r3;
            }
            #pragma unroll
            for (int j = 0; j < 4; j++) MMA(acc[j], a1, b1[j]);
            #pragma unroll
            for (int j = 0; j < 4; j++) MMA(acc[j], a2, b1[j]);
            #pragma unroll
            for (int j = 0; j < 4; j++) MMA(acc[j], a1, b2[j]);
        }
    }
    __syncthreads();    // staging done; reuse dsm as logits

    // scatter logits (descaled): row = tg*16 + qr (+8), col = (nh*4+j)*8 + 2*qc
    const int lr0 = tg * 16 + qr;
    #pragma unroll
    for (int j = 0; j < 4; j++) {
        const int e = (nh * 4 + j) * 8 + 2 * qc;
        lg[lr0 * 65 + e]           = acc[j][0] * WDESC;
        lg[lr0 * 65 + e + 1]       = acc[j][1] * WDESC;
        lg[(lr0 + 8) * 65 + e]     = acc[j][2] * WDESC;
        lg[(lr0 + 8) * 65 + e + 1] = acc[j][3] * WDESC;
    }
    __syncthreads();

    if (tid < BT) {
        float* row = lg + tid * 65;
        float v1 = -1e30f, v2 = -1e30f;
        int i1 = 0, i2 = 0;
        #pragma unroll
        for (int e = 0; e < E_EXP; e++) {
            float v = row[e];
            if (v > v1)      { v2 = v1; i2 = i1; v1 = v; i1 = e; }
            else if (v > v2) { v2 = v;  i2 = e; }
        }
        float Z = 0.f;
        #pragma unroll
        for (int e = 0; e < E_EXP; e++) {
            float ex = expf(row[e] - v1);
            row[e] = ex; Z += ex;
        }
        float rz = 1.0f / Z;
        #pragma unroll
        for (int e = 0; e < E_EXP; e++) row[e] *= rz;
        float s1 = row[i1], s2 = row[i2];
        float inv = 1.0f / (s1 + s2);
        int gt = blk * BT + tid;
        out[2 * gt]     = (float)i1;
        out[2 * gt + 1] = (float)i2;
        out[2 * T_TOKENS + 2 * gt]     = s1 * inv;
        out[2 * T_TOKENS + 2 * gt + 1] = s2 * inv;
        atomicAdd(&s_cnt[i1], 1);
        atomicAdd(&s_cnt[i2], 1);
    }
    __syncthreads();

    if (tid < E_EXP) {
        float sum = 0.f;
        for (int t = 0; t < BT; t++) sum += lg[t * 65 + tid];
        atomicAdd(&g_ssum[tid], sum);
        atomicAdd(&g_cnt[tid], (float)s_cnt[tid]);
    }
    __syncthreads();

    // last CTA computes aux loss
    if (tid == 0) {
        __threadfence();
        s_last = (atomicAdd(&g_done, 1u) == gridDim.x - 1);
    }
    __syncthreads();
    if (s_last) {
        if (tid < E_EXP) lg[tid] = g_ssum[tid] * g_cnt[tid];
        __syncthreads();
        if (tid == 0) {
            float s = 0.f;
            for (int e = 0; e < E_EXP; e++) s += lg[e];
            out[4 * T_TOKENS] = s * (ALPHA * (float)E_EXP /
                ((float)T_TOKENS * 2.0f * (float)T_TOKENS));
        }
    }
}

extern "C" void kernel_launch(void* const* d_in, const int* in_sizes, int n_in,
                              void* d_out, int out_size) {
    const float* x = (const float*)d_in[0];
    const float* w = (const float*)d_in[1];
    float* out = (float*)d_out;
    cudaFuncSetAttribute(gate_kernel,
                         cudaFuncAttributeMaxDynamicSharedMemorySize, SMEM_BYTES);
    prep_w<<<128, 256>>>(w);
    gate_kernel<<<T_TOKENS / BT, NTH, SMEM_BYTES>>>(x, out);
}